// round 1
// baseline (speedup 1.0000x reference)
#include <cuda_runtime.h>

#define BB 2048
#define TT 26
#define DD 512
#define HH 512
#define EE 256
#define NC 97
#define SS 32
#define GG 2048   // 4*H
#define KC 1024   // concat K = D + H

#define BM 128
#define BN 128
#define BKT 16

// ---------------- scratch (static device memory; no allocations) ----------------
__device__ float g_Hp[(size_t)BB*TT*HH];     // 109 MB
__device__ float g_xh[(size_t)BB*KC];        // [context | h]
__device__ float g_c[(size_t)BB*HH];
__device__ float g_ph[(size_t)BB*HH];
__device__ float g_gates[(size_t)BB*GG];
__device__ float g_Wcat[(size_t)GG*KC];      // [W_ih[:, :512] | W_hh]
__device__ float g_bias[GG];                 // b_ih + b_hh
__device__ float g_embproj[(size_t)NC*GG];   // emb_table @ W_ih[:,512:768]^T
__device__ float g_hs[(size_t)BB*SS*HH];     // output hiddens

union F2U { float2 f2; unsigned long long u; float f[2]; };

__device__ __forceinline__ unsigned long long ffma2(unsigned long long a,
                                                    unsigned long long b,
                                                    unsigned long long c) {
    unsigned long long d;
    asm("fma.rn.f32x2 %0, %1, %2, %3;" : "=l"(d) : "l"(a), "l"(b), "l"(c));
    return d;
}

// ---------------- generic NT SGEMM: C[M,N] = A[M,K] * B[N,K]^T (+bias) ----------
// KIND 0: Hp     = batch_H @ W_i2h^T                  M=B*T, N=512, K=512
// KIND 1: ph     = h @ W_h2h^T + b_h2h                M=B,   N=512, K=512  (A = g_xh+512, lda=1024)
// KIND 2: gates  = xh @ Wcat^T + (b_ih+b_hh)          M=B,   N=2048,K=1024
// KIND 3: probs  = hs @ W_gen^T + b_gen               M=B*S, N=97,  K=512
template<int KIND>
__global__ __launch_bounds__(256, 2) void sgemm(
    const float* __restrict__ Xa, const float* __restrict__ Xb,
    const float* __restrict__ Xbias, float* __restrict__ Xc)
{
    constexpr int M   = KIND==0 ? BB*TT : (KIND==3 ? BB*SS : BB);
    constexpr int N   = KIND==2 ? GG : (KIND==3 ? NC : HH);
    constexpr int K   = KIND==2 ? KC : DD;
    constexpr int LDA = (KIND==1 || KIND==2) ? KC : DD;
    constexpr int LDB = KIND==2 ? KC : DD;
    constexpr int LDC = KIND==2 ? GG : (KIND==3 ? NC : HH);
    constexpr bool NTAIL = (N % BN) != 0;
    constexpr bool HASBIAS = (KIND != 0);
    (void)M;

    const float* A    = KIND==0 ? Xa : (KIND==1 ? g_xh + DD : (KIND==2 ? g_xh : g_hs));
    const float* Bp   = KIND==2 ? g_Wcat : Xb;
    const float* bias = KIND==2 ? g_bias : Xbias;
    float*       C    = KIND==0 ? g_Hp : (KIND==1 ? g_ph : (KIND==2 ? g_gates : Xc));

    __shared__ float As[BKT][BM];
    __shared__ float Bs[BKT][BN];

    const int tid = threadIdx.x;
    const int bm  = blockIdx.y * BM;
    const int bn  = blockIdx.x * BN;
    const int tx  = tid & 15;         // N direction
    const int ty  = tid >> 4;         // M direction
    const int lrow = tid >> 2;        // 0..63
    const int lk4  = (tid & 3) << 2;  // 0,4,8,12

    F2U acc[8][4];
    #pragma unroll
    for (int i = 0; i < 8; i++)
        #pragma unroll
        for (int j = 0; j < 4; j++) acc[i][j].f2 = make_float2(0.f, 0.f);

    for (int kt = 0; kt < K; kt += BKT) {
        #pragma unroll
        for (int p = 0; p < 2; p++) {
            int r = lrow + p*64;
            float4 v = *(const float4*)(A + (bm + r)*LDA + kt + lk4);
            As[lk4+0][r] = v.x; As[lk4+1][r] = v.y; As[lk4+2][r] = v.z; As[lk4+3][r] = v.w;
        }
        #pragma unroll
        for (int p = 0; p < 2; p++) {
            int r = lrow + p*64;
            float4 v = make_float4(0.f, 0.f, 0.f, 0.f);
            if (!NTAIL || (bn + r) < N)
                v = *(const float4*)(Bp + (bn + r)*LDB + kt + lk4);
            Bs[lk4+0][r] = v.x; Bs[lk4+1][r] = v.y; Bs[lk4+2][r] = v.z; Bs[lk4+3][r] = v.w;
        }
        __syncthreads();
        #pragma unroll
        for (int k = 0; k < BKT; k++) {
            float4 a0 = *(const float4*)&As[k][ty*8];
            float4 a1 = *(const float4*)&As[k][ty*8+4];
            float4 b0 = *(const float4*)&Bs[k][tx*8];
            float4 b1 = *(const float4*)&Bs[k][tx*8+4];
            F2U bb[4];
            bb[0].f2 = make_float2(b0.x, b0.y);
            bb[1].f2 = make_float2(b0.z, b0.w);
            bb[2].f2 = make_float2(b1.x, b1.y);
            bb[3].f2 = make_float2(b1.z, b1.w);
            float av[8] = {a0.x, a0.y, a0.z, a0.w, a1.x, a1.y, a1.z, a1.w};
            #pragma unroll
            for (int i = 0; i < 8; i++) {
                F2U ad; ad.f2 = make_float2(av[i], av[i]);
                #pragma unroll
                for (int j = 0; j < 4; j++)
                    acc[i][j].u = ffma2(ad.u, bb[j].u, acc[i][j].u);
            }
        }
        __syncthreads();
    }

    #pragma unroll
    for (int i = 0; i < 8; i++) {
        int row = bm + ty*8 + i;
        #pragma unroll
        for (int j = 0; j < 4; j++) {
            #pragma unroll
            for (int h = 0; h < 2; h++) {
                int col = bn + tx*8 + j*2 + h;
                if (!NTAIL || col < N) {
                    float v = acc[i][j].f[h];
                    if (HASBIAS) v += bias[col];
                    C[row*LDC + col] = v;
                }
            }
        }
    }
}

// ---------------- attention (scores + softmax + context), one CTA per batch row --
__global__ __launch_bounds__(256) void attn_step(const float* __restrict__ batch_H,
                                                 const float* __restrict__ wscore)
{
    const int b = blockIdx.x;
    const int tid = threadIdx.x;
    const int warp = tid >> 5, lane = tid & 31;
    __shared__ float sph[HH];
    __shared__ float sw[HH];
    __shared__ float se[32];

    const float* ph = g_ph + (size_t)b * HH;
    for (int i = tid; i < HH; i += 256) { sph[i] = ph[i]; sw[i] = wscore[i]; }
    __syncthreads();

    const float* Hpb = g_Hp + (size_t)b * TT * HH;
    for (int t = warp; t < TT; t += 8) {
        const float* hp = Hpb + t * HH;
        float s = 0.f;
        #pragma unroll 4
        for (int k = lane; k < HH; k += 32)
            s += sw[k] * tanhf(hp[k] + sph[k]);
        #pragma unroll
        for (int o = 16; o > 0; o >>= 1) s += __shfl_down_sync(0xffffffffu, s, o);
        if (lane == 0) se[t] = s;
    }
    __syncthreads();

    if (tid < 32) {
        float v = (tid < TT) ? se[tid] : -1e30f;
        float m = v;
        #pragma unroll
        for (int o = 16; o > 0; o >>= 1) m = fmaxf(m, __shfl_xor_sync(0xffffffffu, m, o));
        float ex = (tid < TT) ? __expf(v - m) : 0.f;
        float sum = ex;
        #pragma unroll
        for (int o = 16; o > 0; o >>= 1) sum += __shfl_xor_sync(0xffffffffu, sum, o);
        if (tid < TT) se[tid] = ex / sum;
    }
    __syncthreads();

    const float* bH = batch_H + (size_t)b * TT * DD;
    for (int d = tid; d < DD; d += 256) {
        float acc = 0.f;
        #pragma unroll
        for (int t = 0; t < TT; t++)
            acc += se[t] * bH[t * DD + d];
        g_xh[(size_t)b * KC + d] = acc;   // context part of xh
    }
}

// ---------------- LSTM pointwise: gates(+emb gather) -> c,h; write hs & xh -------
__global__ void lstm_pointwise(const int* __restrict__ text, int s)
{
    int idx = blockIdx.x * blockDim.x + threadIdx.x;
    if (idx >= BB * HH) return;
    int b = idx >> 9, j = idx & 511;
    int ch = text[b * SS + s];
    const float* ep = g_embproj + (size_t)ch * GG;
    const float* gr = g_gates + (size_t)b * GG;
    float gi = gr[j]          + ep[j];
    float gf = gr[512 + j]    + ep[512 + j];
    float gg = gr[1024 + j]   + ep[1024 + j];
    float go = gr[1536 + j]   + ep[1536 + j];
    float si = 1.f / (1.f + __expf(-gi));
    float sf = 1.f / (1.f + __expf(-gf));
    float so = 1.f / (1.f + __expf(-go));
    float cn = sf * g_c[idx] + si * tanhf(gg);
    float hn = so * tanhf(cn);
    g_c[idx] = cn;
    g_xh[(size_t)b * KC + 512 + j] = hn;
    g_hs[((size_t)b * SS + s) * HH + j] = hn;
}

// ---------------- prep: Wcat, bias sum, zero h/c ---------------------------------
__global__ void prep_wcat(const float* __restrict__ W_ih, const float* __restrict__ W_hh,
                          const float* __restrict__ b_ih, const float* __restrict__ b_hh)
{
    int idx = blockIdx.x * blockDim.x + threadIdx.x;
    if (idx < GG * KC) {
        int n = idx >> 10, k = idx & 1023;
        g_Wcat[idx] = (k < 512) ? W_ih[n * 768 + k] : W_hh[n * 512 + k - 512];
    }
    if (idx < GG) g_bias[idx] = b_ih[idx] + b_hh[idx];
    if (idx < BB * HH) {
        g_c[idx] = 0.f;
        g_xh[(size_t)(idx >> 9) * KC + 512 + (idx & 511)] = 0.f;  // h0 = 0
    }
}

// ---------------- prep: emb_proj[c,n] = sum_e emb[c,e] * W_ih[n, 512+e] ----------
__global__ __launch_bounds__(256) void prep_embproj(const float* __restrict__ emb,
                                                    const float* __restrict__ W_ih)
{
    int c = blockIdx.x;  // 0..96
    __shared__ float s_e[EE];
    for (int i = threadIdx.x; i < EE; i += 256) s_e[i] = emb[c * EE + i];
    __syncthreads();
    for (int n = threadIdx.x; n < GG; n += 256) {
        const float* w = W_ih + (size_t)n * 768 + 512;
        float acc = 0.f;
        #pragma unroll 8
        for (int e = 0; e < EE; e++) acc += s_e[e] * w[e];
        g_embproj[(size_t)c * GG + n] = acc;
    }
}

// ---------------- launch ----------------------------------------------------------
extern "C" void kernel_launch(void* const* d_in, const int* in_sizes, int n_in,
                              void* d_out, int out_size)
{
    const float* batch_H  = (const float*)d_in[0];
    const int*   text     = (const int*)  d_in[1];
    const float* W_i2h    = (const float*)d_in[2];
    const float* W_h2h    = (const float*)d_in[3];
    const float* b_h2h    = (const float*)d_in[4];
    const float* w_score  = (const float*)d_in[5];
    const float* W_ih     = (const float*)d_in[6];
    const float* W_hh     = (const float*)d_in[7];
    const float* b_ih     = (const float*)d_in[8];
    const float* b_hh     = (const float*)d_in[9];
    const float* W_gen    = (const float*)d_in[10];
    const float* b_gen    = (const float*)d_in[11];
    const float* emb      = (const float*)d_in[12];
    float* out = (float*)d_out;

    // prologue
    prep_wcat<<<(GG * KC + 255) / 256, 256>>>(W_ih, W_hh, b_ih, b_hh);
    prep_embproj<<<NC, 256>>>(emb, W_ih);
    // Hp = batch_H @ W_i2h^T
    sgemm<0><<<dim3(HH / BN, (BB * TT) / BM), 256>>>(batch_H, W_i2h, nullptr, nullptr);

    // 32 decode steps
    for (int s = 0; s < SS; s++) {
        sgemm<1><<<dim3(HH / BN, BB / BM), 256>>>(nullptr, W_h2h, b_h2h, nullptr);
        attn_step<<<BB, 256>>>(batch_H, w_score);
        sgemm<2><<<dim3(GG / BN, BB / BM), 256>>>(nullptr, nullptr, nullptr, nullptr);
        lstm_pointwise<<<(BB * HH + 255) / 256, 256>>>(text, s);
    }

    // probs = hs @ W_gen^T + b_gen
    sgemm<3><<<dim3((NC + BN - 1) / BN, (BB * SS) / BM), 256>>>(nullptr, W_gen, b_gen, out);
}

// round 4
// speedup vs baseline: 1.8600x; 1.8600x over previous
#include <cuda_runtime.h>
#include <cuda_bf16.h>
#include <cstdint>

#define BB 2048
#define TT 26
#define DD 512
#define HH 512
#define EE 256
#define NC 97
#define SS 32
#define GG 2048   // 4*H
#define KC 1024   // concat K = D + H

// ---------------- scratch (static device memory; no allocations) ----------------
__device__ float g_Hp[(size_t)BB*TT*HH];
__device__ float g_xh[(size_t)BB*KC];        // [context | h]
__device__ float g_c[(size_t)BB*HH];
__device__ float g_ph[(size_t)BB*HH];
__device__ float g_gates[(size_t)BB*GG];
__device__ float g_Wcat[(size_t)GG*KC];      // [W_ih[:, :512] | W_hh]
__device__ float g_bias[GG];
__device__ float g_embproj[(size_t)NC*GG];
__device__ float g_hs[(size_t)BB*SS*HH];

// ================= helpers =================
__device__ __forceinline__ uint32_t smem_u32(const void* p) {
    uint32_t a;
    asm("{ .reg .u64 t; cvta.to.shared.u64 t, %1; cvt.u32.u64 %0, t; }" : "=r"(a) : "l"(p));
    return a;
}
__device__ __forceinline__ void ldsm_x4(uint32_t& r0, uint32_t& r1, uint32_t& r2, uint32_t& r3,
                                        uint32_t addr) {
    asm volatile("ldmatrix.sync.aligned.m8n8.x4.shared.b16 {%0,%1,%2,%3}, [%4];"
                 : "=r"(r0), "=r"(r1), "=r"(r2), "=r"(r3) : "r"(addr));
}
__device__ __forceinline__ void mma16816(float* d, uint32_t a0, uint32_t a1, uint32_t a2,
                                         uint32_t a3, uint32_t b0, uint32_t b1) {
    asm volatile(
        "mma.sync.aligned.m16n8k16.row.col.f32.bf16.bf16.f32 "
        "{%0,%1,%2,%3}, {%4,%5,%6,%7}, {%8,%9}, {%0,%1,%2,%3};"
        : "+f"(d[0]), "+f"(d[1]), "+f"(d[2]), "+f"(d[3])
        : "r"(a0), "r"(a1), "r"(a2), "r"(a3), "r"(b0), "r"(b1));
}
__device__ __forceinline__ uint32_t pack_bf16(float x, float y) {
    __nv_bfloat162 t = __floats2bfloat162_rn(x, y);
    return *reinterpret_cast<uint32_t*>(&t);
}
// split x = hi + lo (both bf16)
__device__ __forceinline__ void split2(float x, float& h, float& l) {
    __nv_bfloat16 hb = __float2bfloat16_rn(x);
    h = __bfloat162float(hb);
    l = x - h;
}

// ================= bf16-split tensor-core GEMM =================
// C[M,N] = A[M,K] @ B[N,K]^T (+bias), fp32 in/out, 3-term bf16 split internal.
// KIND 0: Hp    = batch_H @ W_i2h^T   M=B*T,  N=512,  K=512
// KIND 1: ph    = h @ W_h2h^T + b     M=B,    N=512,  K=512
// KIND 2: gates = xh @ Wcat^T + b     M=B,    N=2048, K=1024
// KIND 3: probs = hs @ W_gen^T + b    M=B*S,  N=97,   K=512   (odd LDC -> scalar stores)
// Block tile 128(M) x 64(N) x 32(K); 8 warps (4m x 2n), warp tile 32x32.
#define BKP 40   // padded bf16 row length (32 data + 8 pad) -> 80B rows, LDSM conflict-free

template<int KIND>
__global__ __launch_bounds__(256, 1) void mma_gemm(
    const float* __restrict__ Xa, const float* __restrict__ Xb,
    const float* __restrict__ Xbias, float* __restrict__ Xc)
{
    constexpr int N      = KIND==2 ? GG : (KIND==3 ? NC : HH);
    constexpr int K      = KIND==2 ? KC : DD;
    constexpr int LDA    = (KIND==1 || KIND==2) ? KC : DD;
    constexpr int LDB    = KIND==2 ? KC : DD;
    constexpr int LDC    = KIND==2 ? GG : (KIND==3 ? NC : HH);
    constexpr int NCHUNK = K / 32;
    constexpr bool NTAIL = (N % 64) != 0;
    constexpr bool HASBIAS = (KIND != 0);
    // smem layout (bf16 elems) per buffer: A_hi | A_lo | B_hi | B_lo
    constexpr int OF_AH = 0;
    constexpr int OF_AL = 128 * BKP;
    constexpr int OF_BH = 2 * 128 * BKP;
    constexpr int OF_BL = 2 * 128 * BKP + 64 * BKP;
    constexpr int BUFSZ = 2 * 128 * BKP + 2 * 64 * BKP;   // 15360 bf16

    extern __shared__ __nv_bfloat16 sm[];

    const int tid  = threadIdx.x;
    const int wid  = tid >> 5;
    const int lane = tid & 31;
    const int bm   = blockIdx.y * 128;
    const int bn   = blockIdx.x * 64;

    const float* A    = KIND==0 ? Xa : (KIND==1 ? g_xh + DD : (KIND==2 ? g_xh : g_hs));
    const float* Bp   = KIND==2 ? g_Wcat : Xb;
    const float* bias = KIND==2 ? g_bias : Xbias;
    float*       C    = KIND==0 ? g_Hp : (KIND==1 ? g_ph : (KIND==2 ? g_gates : Xc));

    // global load mapping
    const int a_r = tid >> 1;              // 0..127
    const int a_c = (tid & 1) * 16;        // 0 / 16
    const int b_r = tid >> 2;              // 0..63
    const int b_c = (tid & 3) * 8;         // 0,8,16,24

    // warp tile
    const int wm = wid & 3;                // 0..3 -> m offset 32*wm
    const int wn = wid >> 2;               // 0..1 -> n offset 32*wn
    const int m_base = wm * 32;
    const int n_base = wn * 32;

    const uint32_t sb = smem_u32(sm);
    // ldmatrix lane address components (byte offsets)
    uint32_t aRow[2], bRow[2];
    #pragma unroll
    for (int f = 0; f < 2; f++)
        aRow[f] = (uint32_t)((m_base + f*16 + (lane & 15)) * BKP * 2 + (lane >> 4) * 16);
    #pragma unroll
    for (int g = 0; g < 2; g++)
        bRow[g] = (uint32_t)((n_base + g*16 + (lane & 15)) * BKP * 2 + (lane >> 4) * 16);

    float acc[2][4][4];
    #pragma unroll
    for (int f = 0; f < 2; f++)
        #pragma unroll
        for (int g = 0; g < 4; g++)
            #pragma unroll
            for (int i = 0; i < 4; i++) acc[f][g][i] = 0.f;

    float4 pa[4], pb[2];

    // ---- prefetch chunk 0 ----
    {
        const float* ap = A + (size_t)(bm + a_r) * LDA + a_c;
        #pragma unroll
        for (int i = 0; i < 4; i++) pa[i] = *(const float4*)(ap + i * 4);
        #pragma unroll
        for (int i = 0; i < 2; i++) {
            if (!NTAIL || (bn + b_r) < N)
                pb[i] = *(const float4*)(Bp + (size_t)(bn + b_r) * LDB + b_c + i * 4);
            else
                pb[i] = make_float4(0.f, 0.f, 0.f, 0.f);
        }
    }

    auto sts = [&](int buf) {
        __nv_bfloat16* d = sm + buf * BUFSZ;
        #pragma unroll
        for (int i = 0; i < 4; i++) {
            float h0,l0,h1,l1,h2,l2,h3,l3;
            split2(pa[i].x, h0, l0); split2(pa[i].y, h1, l1);
            split2(pa[i].z, h2, l2); split2(pa[i].w, h3, l3);
            uint32_t* ph_ = (uint32_t*)(d + OF_AH + a_r * BKP + a_c + i * 4);
            uint32_t* pl_ = (uint32_t*)(d + OF_AL + a_r * BKP + a_c + i * 4);
            ph_[0] = pack_bf16(h0, h1); ph_[1] = pack_bf16(h2, h3);
            pl_[0] = pack_bf16(l0, l1); pl_[1] = pack_bf16(l2, l3);
        }
        #pragma unroll
        for (int i = 0; i < 2; i++) {
            float h0,l0,h1,l1,h2,l2,h3,l3;
            split2(pb[i].x, h0, l0); split2(pb[i].y, h1, l1);
            split2(pb[i].z, h2, l2); split2(pb[i].w, h3, l3);
            uint32_t* ph_ = (uint32_t*)(d + OF_BH + b_r * BKP + b_c + i * 4);
            uint32_t* pl_ = (uint32_t*)(d + OF_BL + b_r * BKP + b_c + i * 4);
            ph_[0] = pack_bf16(h0, h1); ph_[1] = pack_bf16(h2, h3);
            pl_[0] = pack_bf16(l0, l1); pl_[1] = pack_bf16(l2, l3);
        }
    };

    sts(0);
    __syncthreads();

    for (int c = 0; c < NCHUNK; c++) {
        const int buf = c & 1;
        // prefetch next chunk (global)
        if (c + 1 < NCHUNK) {
            const int kt = (c + 1) * 32;
            const float* ap = A + (size_t)(bm + a_r) * LDA + kt + a_c;
            #pragma unroll
            for (int i = 0; i < 4; i++) pa[i] = *(const float4*)(ap + i * 4);
            #pragma unroll
            for (int i = 0; i < 2; i++) {
                if (!NTAIL || (bn + b_r) < N)
                    pb[i] = *(const float4*)(Bp + (size_t)(bn + b_r) * LDB + kt + b_c + i * 4);
                else
                    pb[i] = make_float4(0.f, 0.f, 0.f, 0.f);
            }
        }

        // compute from buf
        const uint32_t base = sb + (uint32_t)(buf * BUFSZ * 2);
        #pragma unroll
        for (int kk = 0; kk < 2; kk++) {
            const uint32_t ko = kk * 32;   // 16 bf16 = 32 bytes
            uint32_t ah[2][4], al[2][4];
            #pragma unroll
            for (int f = 0; f < 2; f++) {
                ldsm_x4(ah[f][0], ah[f][1], ah[f][2], ah[f][3],
                        base + OF_AH * 2 + aRow[f] + ko);
                ldsm_x4(al[f][0], al[f][1], al[f][2], al[f][3],
                        base + OF_AL * 2 + aRow[f] + ko);
            }
            uint32_t bh[4][2], bl[4][2];
            #pragma unroll
            for (int g2 = 0; g2 < 2; g2++) {
                uint32_t r0, r1, r2, r3;
                ldsm_x4(r0, r1, r2, r3, base + OF_BH * 2 + bRow[g2] + ko);
                bh[g2*2+0][0] = r0; bh[g2*2+0][1] = r2;
                bh[g2*2+1][0] = r1; bh[g2*2+1][1] = r3;
                ldsm_x4(r0, r1, r2, r3, base + OF_BL * 2 + bRow[g2] + ko);
                bl[g2*2+0][0] = r0; bl[g2*2+0][1] = r2;
                bl[g2*2+1][0] = r1; bl[g2*2+1][1] = r3;
            }
            #pragma unroll
            for (int f = 0; f < 2; f++)
                #pragma unroll
                for (int g = 0; g < 4; g++) {
                    mma16816(acc[f][g], ah[f][0], ah[f][1], ah[f][2], ah[f][3],
                             bh[g][0], bh[g][1]);
                    mma16816(acc[f][g], al[f][0], al[f][1], al[f][2], al[f][3],
                             bh[g][0], bh[g][1]);
                    mma16816(acc[f][g], ah[f][0], ah[f][1], ah[f][2], ah[f][3],
                             bl[g][0], bl[g][1]);
                }
        }

        // store next chunk into other buffer
        if (c + 1 < NCHUNK) sts((c + 1) & 1);
        __syncthreads();
    }

    // ---- epilogue ----
    #pragma unroll
    for (int f = 0; f < 2; f++) {
        const int row0 = bm + m_base + f * 16 + (lane >> 2);
        #pragma unroll
        for (int g = 0; g < 4; g++) {
            const int col = bn + n_base + g * 8 + (lane & 3) * 2;
            if (!NTAIL) {
                // even LDC: vectorized float2 stores (8B-aligned)
                float b0 = 0.f, b1 = 0.f;
                if (HASBIAS) { b0 = bias[col]; b1 = bias[col + 1]; }
                *(float2*)(C + (size_t)row0 * LDC + col) =
                    make_float2(acc[f][g][0] + b0, acc[f][g][1] + b1);
                *(float2*)(C + (size_t)(row0 + 8) * LDC + col) =
                    make_float2(acc[f][g][2] + b0, acc[f][g][3] + b1);
            } else {
                // odd LDC (N=97): scalar stores only
                #pragma unroll
                for (int h = 0; h < 2; h++) {
                    int cc = col + h;
                    if (cc < N) {
                        float bb = HASBIAS ? bias[cc] : 0.f;
                        C[(size_t)row0 * LDC + cc]       = acc[f][g][0 + h] + bb;
                        C[(size_t)(row0 + 8) * LDC + cc] = acc[f][g][2 + h] + bb;
                    }
                }
            }
        }
    }
}

// ---------------- attention (scores + softmax + context), one CTA per batch row --
__global__ __launch_bounds__(256) void attn_step(const float* __restrict__ batch_H,
                                                 const float* __restrict__ wscore)
{
    const int b = blockIdx.x;
    const int tid = threadIdx.x;
    const int warp = tid >> 5, lane = tid & 31;
    __shared__ float sph[HH];
    __shared__ float sw[HH];
    __shared__ float se[32];

    const float* ph = g_ph + (size_t)b * HH;
    for (int i = tid; i < HH; i += 256) { sph[i] = ph[i]; sw[i] = wscore[i]; }
    __syncthreads();

    const float* Hpb = g_Hp + (size_t)b * TT * HH;
    for (int t = warp; t < TT; t += 8) {
        const float* hp = Hpb + t * HH;
        float s = 0.f;
        #pragma unroll 4
        for (int k = lane; k < HH; k += 32)
            s += sw[k] * tanhf(hp[k] + sph[k]);
        #pragma unroll
        for (int o = 16; o > 0; o >>= 1) s += __shfl_down_sync(0xffffffffu, s, o);
        if (lane == 0) se[t] = s;
    }
    __syncthreads();

    if (tid < 32) {
        float v = (tid < TT) ? se[tid] : -1e30f;
        float m = v;
        #pragma unroll
        for (int o = 16; o > 0; o >>= 1) m = fmaxf(m, __shfl_xor_sync(0xffffffffu, m, o));
        float ex = (tid < TT) ? __expf(v - m) : 0.f;
        float sum = ex;
        #pragma unroll
        for (int o = 16; o > 0; o >>= 1) sum += __shfl_xor_sync(0xffffffffu, sum, o);
        if (tid < TT) se[tid] = ex / sum;
    }
    __syncthreads();

    const float* bH = batch_H + (size_t)b * TT * DD;
    for (int d = tid; d < DD; d += 256) {
        float acc = 0.f;
        #pragma unroll
        for (int t = 0; t < TT; t++)
            acc += se[t] * bH[t * DD + d];
        g_xh[(size_t)b * KC + d] = acc;
    }
}

// ---------------- LSTM pointwise -------------------------------------------------
__global__ void lstm_pointwise(const int* __restrict__ text, int s)
{
    int idx = blockIdx.x * blockDim.x + threadIdx.x;
    if (idx >= BB * HH) return;
    int b = idx >> 9, j = idx & 511;
    int ch = text[b * SS + s];
    const float* ep = g_embproj + (size_t)ch * GG;
    const float* gr = g_gates + (size_t)b * GG;
    float gi = gr[j]          + ep[j];
    float gf = gr[512 + j]    + ep[512 + j];
    float gg = gr[1024 + j]   + ep[1024 + j];
    float go = gr[1536 + j]   + ep[1536 + j];
    float si = 1.f / (1.f + __expf(-gi));
    float sf = 1.f / (1.f + __expf(-gf));
    float so = 1.f / (1.f + __expf(-go));
    float cn = sf * g_c[idx] + si * tanhf(gg);
    float hn = so * tanhf(cn);
    g_c[idx] = cn;
    g_xh[(size_t)b * KC + 512 + j] = hn;
    g_hs[((size_t)b * SS + s) * HH + j] = hn;
}

// ---------------- prep kernels ----------------------------------------------------
__global__ void prep_wcat(const float* __restrict__ W_ih, const float* __restrict__ W_hh,
                          const float* __restrict__ b_ih, const float* __restrict__ b_hh)
{
    int idx = blockIdx.x * blockDim.x + threadIdx.x;
    if (idx < GG * KC) {
        int n = idx >> 10, k = idx & 1023;
        g_Wcat[idx] = (k < 512) ? W_ih[n * 768 + k] : W_hh[n * 512 + k - 512];
    }
    if (idx < GG) g_bias[idx] = b_ih[idx] + b_hh[idx];
    if (idx < BB * HH) {
        g_c[idx] = 0.f;
        g_xh[(size_t)(idx >> 9) * KC + 512 + (idx & 511)] = 0.f;
    }
}

__global__ __launch_bounds__(256) void prep_embproj(const float* __restrict__ emb,
                                                    const float* __restrict__ W_ih)
{
    int c = blockIdx.x;
    __shared__ float s_e[EE];
    for (int i = threadIdx.x; i < EE; i += 256) s_e[i] = emb[c * EE + i];
    __syncthreads();
    for (int n = threadIdx.x; n < GG; n += 256) {
        const float* w = W_ih + (size_t)n * 768 + 512;
        float acc = 0.f;
        #pragma unroll 8
        for (int e = 0; e < EE; e++) acc += s_e[e] * w[e];
        g_embproj[(size_t)c * GG + n] = acc;
    }
}

// ---------------- launch -----------------------------------------------------------
extern "C" void kernel_launch(void* const* d_in, const int* in_sizes, int n_in,
                              void* d_out, int out_size)
{
    const float* batch_H  = (const float*)d_in[0];
    const int*   text     = (const int*)  d_in[1];
    const float* W_i2h    = (const float*)d_in[2];
    const float* W_h2h    = (const float*)d_in[3];
    const float* b_h2h    = (const float*)d_in[4];
    const float* w_score  = (const float*)d_in[5];
    const float* W_ih     = (const float*)d_in[6];
    const float* W_hh     = (const float*)d_in[7];
    const float* b_ih     = (const float*)d_in[8];
    const float* b_hh     = (const float*)d_in[9];
    const float* W_gen    = (const float*)d_in[10];
    const float* b_gen    = (const float*)d_in[11];
    const float* emb      = (const float*)d_in[12];
    float* out = (float*)d_out;

    const int smemB = 2 * (2*128*BKP + 2*64*BKP) * 2;   // 61440 bytes
    cudaFuncSetAttribute(mma_gemm<0>, cudaFuncAttributeMaxDynamicSharedMemorySize, smemB);
    cudaFuncSetAttribute(mma_gemm<1>, cudaFuncAttributeMaxDynamicSharedMemorySize, smemB);
    cudaFuncSetAttribute(mma_gemm<2>, cudaFuncAttributeMaxDynamicSharedMemorySize, smemB);
    cudaFuncSetAttribute(mma_gemm<3>, cudaFuncAttributeMaxDynamicSharedMemorySize, smemB);

    // prologue
    prep_wcat<<<(GG * KC + 255) / 256, 256>>>(W_ih, W_hh, b_ih, b_hh);
    prep_embproj<<<NC, 256>>>(emb, W_ih);
    // Hp = batch_H @ W_i2h^T   [53248 x 512]
    mma_gemm<0><<<dim3(HH/64, (BB*TT)/128), 256, smemB>>>(batch_H, W_i2h, nullptr, nullptr);

    // 32 decode steps
    for (int s = 0; s < SS; s++) {
        mma_gemm<1><<<dim3(HH/64, BB/128), 256, smemB>>>(nullptr, W_h2h, b_h2h, nullptr);
        attn_step<<<BB, 256>>>(batch_H, w_score);
        mma_gemm<2><<<dim3(GG/64, BB/128), 256, smemB>>>(nullptr, nullptr, nullptr, nullptr);
        lstm_pointwise<<<(BB * HH + 255) / 256, 256>>>(text, s);
    }

    // probs = hs @ W_gen^T + b_gen   [65536 x 97]
    mma_gemm<3><<<dim3(2, (BB*SS)/128), 256, smemB>>>(nullptr, W_gen, b_gen, out);
}